// round 15
// baseline (speedup 1.0000x reference)
#include <cuda_runtime.h>
#include <cuda_fp16.h>
#include <math.h>
#include <stdint.h>

#define NN 50000
#define EE 320000
constexpr int DN   = 256;
constexpr int DEF  = 128;
constexpr int TD   = 64;
constexpr int DEIN = 192;
constexpr int H    = 8;

// ---------------- scratch ---------------------------------------------------
// Q/K/V stored as half2-packed uint32 (col pairs): [NN][128]
__device__ uint32_t g_Qh[(size_t)NN * DN / 2];
__device__ uint32_t g_Kh[(size_t)NN * DN / 2];
__device__ uint32_t g_Vh[(size_t)NN * DN / 2];
__device__ float    g_acc[(size_t)NN * DN];
__device__ float    g_denom[(size_t)NN * H];

// ---------------- helpers ---------------------------------------------------
__device__ __forceinline__ void red_add_v4(float* p, float4 v) {
    asm volatile("red.global.add.v4.f32 [%0], {%1,%2,%3,%4};"
                 :: "l"(p), "f"(v.x), "f"(v.y), "f"(v.z), "f"(v.w) : "memory");
}
__device__ __forceinline__ void red_add_f(float* p, float v) {
    asm volatile("red.global.add.f32 [%0], %1;" :: "l"(p), "f"(v) : "memory");
}
__device__ __forceinline__ uint32_t pack2(float lo, float hi) {
    __half2 h = __floats2half2_rn(lo, hi);
    return *(uint32_t*)&h;
}
// load 4 cols (2 packed uint32) -> float4
__device__ __forceinline__ float4 ld_h4(const uint32_t* p) {
    uint2 u = *(const uint2*)p;
    float2 a = __half22float2(*(__half2*)&u.x);
    float2 b = __half22float2(*(__half2*)&u.y);
    return make_float4(a.x, a.y, b.x, b.y);
}
// fp16 mma: D(16x8,f32) += A(16x16,f16) * B(16x8,f16)
__device__ __forceinline__ void mma_f16(float* c, const uint32_t* a, const uint32_t* b) {
    asm volatile(
        "mma.sync.aligned.m16n8k16.row.col.f32.f16.f16.f32 "
        "{%0,%1,%2,%3}, {%4,%5,%6,%7}, {%8,%9}, {%0,%1,%2,%3};"
        : "+f"(c[0]), "+f"(c[1]), "+f"(c[2]), "+f"(c[3])
        : "r"(a[0]), "r"(a[1]), "r"(a[2]), "r"(a[3]), "r"(b[0]), "r"(b[1]));
}

// ---------------- smem layout -----------------------------------------------
constexpr int SM_T  = 0;
constexpr int SM_W  = 512;
constexpr int SM_BT = 768;
constexpr int SM_A0 = 1024;
constexpr int SM_A1 = SM_A0 + 8192;
constexpr int SM_B0 = SM_A1 + 8192;
constexpr int SM_B1 = SM_B0 + 8192;
constexpr int SMEM_NODE = SM_B1 + 8192;           // 33792
constexpr int EP_STRIDE = 132;
constexpr int SMEM_EDGE = SM_A0 + 128 * EP_STRIDE * 4;  // 68608

// ---- fp16 fragment smem layouts (same as R14) --------------------------------
__device__ __forceinline__ void stA_f16(uint32_t* sA, int i, float4 v) {
    int tid = threadIdx.x;
    int R0 = tid >> 3, c4 = tid & 7;
    int ks = c4 >> 2, c03 = c4 & 3;
    int r = R0 & 15;
    int mt = (R0 >> 4) + 2 * i;
    int base = ((ks * 8 + mt) * 32 + (r & 7) * 4 + 2 * (c03 & 1)) * 4
             + (r >> 3) + 2 * (c03 >> 1);
    uint32_t h0 = pack2(v.x, v.y);
    uint32_t h1 = pack2(v.z, v.w);
    uint32_t* p = sA + base;
    int xc = ks;
    p[4 * xc]     = xc ? h1 : h0;
    p[4 - 4 * xc] = xc ? h0 : h1;
}

__device__ __forceinline__ void stage_A_node(uint32_t* sA, const float* __restrict__ X,
                                             int m0, int k0) {
    int tid = threadIdx.x;
    int R0 = tid >> 3, c4 = tid & 7;
#pragma unroll
    for (int i = 0; i < 4; i++) {
        int node = m0 + R0 + 32 * i;
        float4 v = make_float4(0.f, 0.f, 0.f, 0.f);
        if (node < NN) v = *(const float4*)&X[(size_t)node * DN + k0 + c4 * 4];
        stA_f16(sA, i, v);
    }
}

__device__ __forceinline__ void stage_B_w(uint32_t* sB, const float* __restrict__ W,
                                          int n0, int k0, int stride) {
    int tid = threadIdx.x;
    int N0 = tid >> 3, c4 = tid & 7;
    int ks = c4 >> 2, c03 = c4 & 3;
#pragma unroll
    for (int i = 0; i < 4; i++) {
        int n = N0 + 32 * i;
        float4 v = *(const float4*)&W[(size_t)(n0 + n) * stride + k0 + c4 * 4];
        int nt = n >> 3;
        int base = ((ks * 16 + nt) * 32 + (n & 7) * 4 + 2 * (c03 & 1)) * 2
                 + (c03 >> 1);
        uint32_t h0 = pack2(v.x, v.y);
        uint32_t h1 = pack2(v.z, v.w);
        uint32_t* p = sB + base;
        int xc = ks;
        p[2 * xc]     = xc ? h1 : h0;
        p[2 - 2 * xc] = xc ? h0 : h1;
    }
}

__device__ __forceinline__ void stage_A_edge(uint32_t* sA, const char* smem,
                                             const float* __restrict__ ef,
                                             int e0, int c) {
    int tid = threadIdx.x;
    if (c < 2) {
        const float* sT  = (const float*)(smem + SM_T);
        const float* sW  = (const float*)(smem + SM_W);
        const float* sBt = (const float*)(smem + SM_BT);
        int lane = tid & 31, wq = tid >> 5;
        int k0 = c * 32;
        int p = lane & 7;
        int r0 = (lane >> 3) & 1, r3 = (lane >> 4) & 1;
        int mt = wq;
#pragma unroll
        for (int i = 0; i < 8; i++) {
            int ks = i >> 2;
            int r = r0 | ((i & 3) << 1) | (r3 << 3);
            int row = r | (mt << 4);
            int kk = k0 + (ks * 8 + p) * 2;
            float t = sT[row];
            float v0 = __cosf(t * sW[kk]     + sBt[kk]);
            float v1 = __cosf(t * sW[kk + 1] + sBt[kk + 1]);
            int addr = ((ks * 8 + mt) * 32 + (r & 7) * 4 + (p & 3)) * 4
                     + (r >> 3) + 2 * ((p >> 2) & 1);
            sA[addr] = pack2(v0, v1);
        }
    } else {
        int k0 = c * 32 - 64;
        int R0 = tid >> 3, c4 = tid & 7;
#pragma unroll
        for (int i = 0; i < 4; i++) {
            int row = R0 + 32 * i;
            float4 v = *(const float4*)&ef[(size_t)(e0 + row) * DEF + k0 + c4 * 4];
            stA_f16(sA, i, v);
        }
    }
}

__device__ __forceinline__ void chunk_mma(const uint32_t* sA, const uint32_t* sB,
                                          int warpM, int warpN, int lane,
                                          float acc[2][8][4]) {
#pragma unroll
    for (int ks = 0; ks < 2; ks++) {
        uint32_t af[2][4];
#pragma unroll
        for (int m = 0; m < 2; m++)
            *(uint4*)af[m] = *(const uint4*)&sA[((ks * 8 + warpM * 2 + m) * 32 + lane) * 4];
        uint32_t bf[8][2];
#pragma unroll
        for (int j = 0; j < 8; j++)
            *(uint2*)bf[j] = *(const uint2*)&sB[((ks * 16 + warpN * 8 + j) * 32 + lane) * 2];
#pragma unroll
        for (int m = 0; m < 2; m++)
#pragma unroll
            for (int j = 0; j < 8; j++) mma_f16(acc[m][j], af[m], bf[j]);
    }
}

// ---------------- node GEMMs: Q,K,V (fp16 out) + skip (fp32 out) -------------
__global__ __launch_bounds__(256, 2)
void k_node_mma(const float* __restrict__ X,
                const float* __restrict__ Wq, const float* __restrict__ Wk,
                const float* __restrict__ Wv, const float* __restrict__ Ws,
                const float* __restrict__ bq, const float* __restrict__ bk,
                const float* __restrict__ bv, const float* __restrict__ bs,
                float* __restrict__ out) {
    extern __shared__ char smem[];
    const int tid = threadIdx.x, wid = tid >> 5, lane = tid & 31;
    const int warpM = wid & 3, warpN = wid >> 2;
    const int m0 = blockIdx.y * 128;
    const int bx = blockIdx.x, mat = bx >> 1, n0 = (bx & 1) * 128;
    const float* W; const float* bias; uint32_t* dsth = nullptr;
    if      (mat == 0) { W = Wq; bias = bq; dsth = g_Qh; }
    else if (mat == 1) { W = Wk; bias = bk; dsth = g_Kh; }
    else if (mat == 2) { W = Wv; bias = bv; dsth = g_Vh; }
    else               { W = Ws; bias = bs; }

    if (bx == 4) {
        int i4 = m0 * 2 + tid;
        if (i4 < NN * H / 4)
            ((float4*)g_denom)[i4] = make_float4(0.f, 0.f, 0.f, 0.f);
    }

    uint32_t* sA[2] = { (uint32_t*)(smem + SM_A0), (uint32_t*)(smem + SM_A1) };
    uint32_t* sB[2] = { (uint32_t*)(smem + SM_B0), (uint32_t*)(smem + SM_B1) };

    float acc[2][8][4] = {};

    stage_A_node(sA[0], X, m0, 0);
    stage_B_w(sB[0], W, n0, 0, DN);
    __syncthreads();

    for (int c = 0; c < 8; c++) {
        chunk_mma(sA[c & 1], sB[c & 1], warpM, warpN, lane, acc);
        if (c < 7) {
            stage_A_node(sA[(c + 1) & 1], X, m0, (c + 1) * 32);
            stage_B_w(sB[(c + 1) & 1], W, n0, (c + 1) * 32, DN);
        }
        __syncthreads();
    }

    float2 bb[8];
#pragma unroll
    for (int j = 0; j < 8; j++)
        bb[j] = *(const float2*)&bias[n0 + warpN * 64 + j * 8 + (lane & 3) * 2];
#pragma unroll
    for (int m = 0; m < 2; m++)
#pragma unroll
        for (int rv = 0; rv < 2; rv++) {
            int node = m0 + warpM * 32 + m * 16 + rv * 8 + (lane >> 2);
            if (node >= NN) continue;
            if (mat == 3) {
                float* dp = out + (size_t)node * DN + n0 + warpN * 64 + (lane & 3) * 2;
#pragma unroll
                for (int j = 0; j < 8; j++) {
                    float2 o = make_float2(acc[m][j][rv * 2 + 0] + bb[j].x,
                                           acc[m][j][rv * 2 + 1] + bb[j].y);
                    *(float2*)(dp + j * 8) = o;
                }
            } else {
                // packed fp16 store: col pair -> one uint32
                uint32_t* dp = dsth + (size_t)node * 128
                             + ((n0 + warpN * 64) >> 1) + (lane & 3);
#pragma unroll
                for (int j = 0; j < 8; j++)
                    dp[j * 4] = pack2(acc[m][j][rv * 2 + 0] + bb[j].x,
                                      acc[m][j][rv * 2 + 1] + bb[j].y);
                if (mat == 2) {
                    float* zp = g_acc + (size_t)node * DN + n0 + warpN * 64 + (lane & 3) * 2;
#pragma unroll
                    for (int j = 0; j < 8; j++)
                        *(float2*)(zp + j * 8) = make_float2(0.f, 0.f);
                }
            }
        }
}

// ------- edge GEMM + fused time-enc + alpha + exp + scatter-aggregate -------
__global__ __launch_bounds__(256, 2)
void k_edge_mma(const float* __restrict__ ef, const int* __restrict__ etup,
                const float* __restrict__ We, const float* __restrict__ times,
                const float* __restrict__ wt, const float* __restrict__ bt) {
    extern __shared__ char smem[];
    const int tid = threadIdx.x, wid = tid >> 5, lane = tid & 31;
    const int warpM = wid & 3, warpN = wid >> 2;
    const int e0 = blockIdx.y * 128;
    const int n0 = blockIdx.x * 128;

    if (tid < 128) ((float*)(smem + SM_T))[tid] = times[e0 + tid];
    if (tid < 64) {
        ((float*)(smem + SM_W))[tid]  = wt[tid];
        ((float*)(smem + SM_BT))[tid] = bt[tid];
    }
    __syncthreads();

    uint32_t* sA[2] = { (uint32_t*)(smem + SM_A0), (uint32_t*)(smem + SM_A1) };
    uint32_t* sB[2] = { (uint32_t*)(smem + SM_B0), (uint32_t*)(smem + SM_B1) };

    float acc[2][8][4] = {};

    stage_A_edge(sA[0], smem, ef, e0, 0);
    stage_B_w(sB[0], We, n0, 0, DEIN);
    __syncthreads();

    for (int c = 0; c < 6; c++) {
        chunk_mma(sA[c & 1], sB[c & 1], warpM, warpN, lane, acc);
        if (c < 5) {
            stage_A_edge(sA[(c + 1) & 1], smem, ef, e0, c + 1);
            stage_B_w(sB[(c + 1) & 1], We, n0, (c + 1) * 32, DEIN);
        }
        __syncthreads();
    }

    // ---- transpose acc fragments into smem ep tile ----
    float* sEp = (float*)(smem + SM_A0);
#pragma unroll
    for (int m = 0; m < 2; m++)
#pragma unroll
        for (int rv = 0; rv < 2; rv++) {
            int row = warpM * 32 + m * 16 + rv * 8 + (lane >> 2);
            int col = warpN * 64 + (lane & 3) * 2;
#pragma unroll
            for (int j = 0; j < 8; j++)
                *(float2*)&sEp[row * EP_STRIDE + col + j * 8] =
                    make_float2(acc[m][j][rv * 2 + 0], acc[m][j][rv * 2 + 1]);
        }
    __syncthreads();

    // ---- warp-per-edge epilogue, unroll 4, fp16 gathers ----
    const float scale = 0.17677669529663687f;
    const int hb = (n0 >> 5) + (lane >> 3);
    const int colg = n0 + lane * 4;
    const int cidx = colg >> 1;            // uint32 index into packed rows

    int my_sd = etup[(lane >> 4) * EE + e0 + wid * 16 + (lane & 15)];

#pragma unroll
    for (int t = 0; t < 16; t += 4) {
        int s[4], d[4];
#pragma unroll
        for (int u = 0; u < 4; u++) {
            s[u] = __shfl_sync(0xffffffffu, my_sd, t + u);
            d[u] = __shfl_sync(0xffffffffu, my_sd, 16 + t + u);
        }
        float4 ep[4], qv[4], kv[4], vv[4];
#pragma unroll
        for (int u = 0; u < 4; u++) {
            int eloc = wid * 16 + t + u;
            ep[u] = *(const float4*)&sEp[eloc * EP_STRIDE + lane * 4];
            qv[u] = ld_h4(g_Qh + (size_t)d[u] * 128 + cidx);
            kv[u] = ld_h4(g_Kh + (size_t)s[u] * 128 + cidx);
            vv[u] = ld_h4(g_Vh + (size_t)s[u] * 128 + cidx);
        }
        float p[4];
#pragma unroll
        for (int u = 0; u < 4; u++)
            p[u] = qv[u].x * (kv[u].x + ep[u].x) + qv[u].y * (kv[u].y + ep[u].y)
                 + qv[u].z * (kv[u].z + ep[u].z) + qv[u].w * (kv[u].w + ep[u].w);
#pragma unroll
        for (int m = 1; m <= 4; m <<= 1)
#pragma unroll
            for (int u = 0; u < 4; u++)
                p[u] += __shfl_xor_sync(0xffffffffu, p[u], m);
#pragma unroll
        for (int u = 0; u < 4; u++) {
            float wgt = __expf(p[u] * scale);
            float4 r = make_float4(wgt * (vv[u].x + ep[u].x),
                                   wgt * (vv[u].y + ep[u].y),
                                   wgt * (vv[u].z + ep[u].z),
                                   wgt * (vv[u].w + ep[u].w));
            red_add_v4(&g_acc[(size_t)d[u] * DN + colg], r);
            if ((lane & 7) == 0) red_add_f(&g_denom[d[u] * H + hb], wgt);
        }
    }
}

// ---------------- finalize: out = skip + acc/denom ---------------------------
__global__ __launch_bounds__(256)
void k_finalize(float* __restrict__ out) {
    int idx = blockIdx.x * blockDim.x + threadIdx.x;
    if (idx >= NN * DN / 4) return;
    int node = idx >> 6;
    int col4 = idx & 63;
    int head = col4 >> 3;
    float den = g_denom[node * H + head] + 1e-16f;
    float inv = 1.0f / den;
    float4 a = ((const float4*)g_acc)[idx];
    float4 o = ((float4*)out)[idx];
    o.x += a.x * inv; o.y += a.y * inv; o.z += a.z * inv; o.w += a.w * inv;
    ((float4*)out)[idx] = o;
}

// ---------------- launch ----------------------------------------------------
extern "C" void kernel_launch(void* const* d_in, const int* in_sizes, int n_in,
                              void* d_out, int out_size) {
    const int*   etup       = (const int*)  d_in[0];
    const float* edge_feats = (const float*)d_in[1];
    const float* times      = (const float*)d_in[2];
    const float* X          = (const float*)d_in[3];
    const float* w_time     = (const float*)d_in[4];
    const float* b_time     = (const float*)d_in[5];
    const float* Wq         = (const float*)d_in[6];
    const float* bq         = (const float*)d_in[7];
    const float* Wk         = (const float*)d_in[8];
    const float* bk         = (const float*)d_in[9];
    const float* Wv         = (const float*)d_in[10];
    const float* bv         = (const float*)d_in[11];
    const float* We         = (const float*)d_in[12];
    const float* Ws         = (const float*)d_in[13];
    const float* bs         = (const float*)d_in[14];
    float* out = (float*)d_out;

    cudaFuncSetAttribute(k_node_mma, cudaFuncAttributeMaxDynamicSharedMemorySize, SMEM_NODE);
    cudaFuncSetAttribute(k_edge_mma, cudaFuncAttributeMaxDynamicSharedMemorySize, SMEM_EDGE);

    k_node_mma<<<dim3(8, (NN + 127) / 128), 256, SMEM_NODE>>>(
        X, Wq, Wk, Wv, Ws, bq, bk, bv, bs, out);
    k_edge_mma<<<dim3(2, EE / 128), 256, SMEM_EDGE>>>(
        edge_feats, etup, We, times, w_time, b_time);
    k_finalize<<<(NN * DN / 4 + 255) / 256, 256>>>(out);
}

// round 16
// speedup vs baseline: 1.4217x; 1.4217x over previous
#include <cuda_runtime.h>
#include <cuda_fp16.h>
#include <math.h>
#include <stdint.h>

#define NN 50000
#define EE 320000
constexpr int DN   = 256;
constexpr int DEF  = 128;
constexpr int TD   = 64;
constexpr int DEIN = 192;
constexpr int H    = 8;

// ---------------- scratch ---------------------------------------------------
__device__ float g_Q[(size_t)NN * DN];
__device__ float g_K[(size_t)NN * DN];
__device__ float g_V[(size_t)NN * DN];
__device__ float g_acc[(size_t)NN * DN];
__device__ float g_denom[(size_t)NN * H];

// ---------------- helpers ---------------------------------------------------
__device__ __forceinline__ void red_add_v4(float* p, float4 v) {
    asm volatile("red.global.add.v4.f32 [%0], {%1,%2,%3,%4};"
                 :: "l"(p), "f"(v.x), "f"(v.y), "f"(v.z), "f"(v.w) : "memory");
}
__device__ __forceinline__ void red_add_f(float* p, float v) {
    asm volatile("red.global.add.f32 [%0], %1;" :: "l"(p), "f"(v) : "memory");
}
__device__ __forceinline__ uint32_t pack2(float lo, float hi) {
    __half2 h = __floats2half2_rn(lo, hi);
    return *(uint32_t*)&h;
}
// fp16 mma: D(16x8,f32) += A(16x16,f16) * B(16x8,f16)
__device__ __forceinline__ void mma_f16(float* c, const uint32_t* a, const uint32_t* b) {
    asm volatile(
        "mma.sync.aligned.m16n8k16.row.col.f32.f16.f16.f32 "
        "{%0,%1,%2,%3}, {%4,%5,%6,%7}, {%8,%9}, {%0,%1,%2,%3};"
        : "+f"(c[0]), "+f"(c[1]), "+f"(c[2]), "+f"(c[3])
        : "r"(a[0]), "r"(a[1]), "r"(a[2]), "r"(a[3]), "r"(b[0]), "r"(b[1]));
}

// ---------------- smem layout -----------------------------------------------
// K-chunk = 64: A bufs 16KB (128x64 fp16), B bufs 16KB (128x64 fp16)
constexpr int SM_T  = 0;
constexpr int SM_W  = 512;
constexpr int SM_BT = 768;
constexpr int SM_A0 = 1024;
constexpr int SM_A1 = SM_A0 + 16384;
constexpr int SM_B0 = SM_A1 + 16384;
constexpr int SM_B1 = SM_B0 + 16384;
constexpr int SMEM_NODE = SM_B1 + 16384;          // 66560
constexpr int EP_STRIDE = 132;
constexpr int SMEM_EDGE = SM_A0 + 128 * EP_STRIDE * 4;  // 68608
// ks stride inside a buffer: A ((ks*8+mt)*32+ln)*4 -> 1024 u32; 32 cols = 2 ks = 2048
constexpr int KS32 = 2048;

// ---- fp16 fragment smem staging (32-col sub-chunk units, same as R14) -------
__device__ __forceinline__ void stA_f16(uint32_t* sA, int i, float4 v) {
    int tid = threadIdx.x;
    int R0 = tid >> 3, c4 = tid & 7;
    int ks = c4 >> 2, c03 = c4 & 3;
    int r = R0 & 15;
    int mt = (R0 >> 4) + 2 * i;
    int base = ((ks * 8 + mt) * 32 + (r & 7) * 4 + 2 * (c03 & 1)) * 4
             + (r >> 3) + 2 * (c03 >> 1);
    uint32_t h0 = pack2(v.x, v.y);
    uint32_t h1 = pack2(v.z, v.w);
    uint32_t* p = sA + base;
    int xc = ks;
    p[4 * xc]     = xc ? h1 : h0;
    p[4 - 4 * xc] = xc ? h0 : h1;
}

__device__ __forceinline__ void stage_A_node(uint32_t* sA, const float* __restrict__ X,
                                             int m0, int k0) {
    int tid = threadIdx.x;
    int R0 = tid >> 3, c4 = tid & 7;
#pragma unroll
    for (int i = 0; i < 4; i++) {
        int node = m0 + R0 + 32 * i;
        float4 v = make_float4(0.f, 0.f, 0.f, 0.f);
        if (node < NN) v = *(const float4*)&X[(size_t)node * DN + k0 + c4 * 4];
        stA_f16(sA, i, v);
    }
}

__device__ __forceinline__ void stage_B_w(uint32_t* sB, const float* __restrict__ W,
                                          int n0, int k0, int stride) {
    int tid = threadIdx.x;
    int N0 = tid >> 3, c4 = tid & 7;
    int ks = c4 >> 2, c03 = c4 & 3;
#pragma unroll
    for (int i = 0; i < 4; i++) {
        int n = N0 + 32 * i;
        float4 v = *(const float4*)&W[(size_t)(n0 + n) * stride + k0 + c4 * 4];
        int nt = n >> 3;
        int base = ((ks * 16 + nt) * 32 + (n & 7) * 4 + 2 * (c03 & 1)) * 2
                 + (c03 >> 1);
        uint32_t h0 = pack2(v.x, v.y);
        uint32_t h1 = pack2(v.z, v.w);
        uint32_t* p = sB + base;
        int xc = ks;
        p[2 * xc]     = xc ? h1 : h0;
        p[2 - 2 * xc] = xc ? h0 : h1;
    }
}

// 32-col sub-chunk of edge A: sub<2 -> cos cols, else ef cols
__device__ __forceinline__ void stage_A_edge32(uint32_t* sA, const char* smem,
                                               const float* __restrict__ ef,
                                               int e0, int sub) {
    int tid = threadIdx.x;
    if (sub < 2) {
        const float* sT  = (const float*)(smem + SM_T);
        const float* sW  = (const float*)(smem + SM_W);
        const float* sBt = (const float*)(smem + SM_BT);
        int lane = tid & 31, wq = tid >> 5;
        int k0 = sub * 32;
        int p = lane & 7;
        int r0 = (lane >> 3) & 1, r3 = (lane >> 4) & 1;
        int mt = wq;
#pragma unroll
        for (int i = 0; i < 8; i++) {
            int ks = i >> 2;
            int r = r0 | ((i & 3) << 1) | (r3 << 3);
            int row = r | (mt << 4);
            int kk = k0 + (ks * 8 + p) * 2;
            float t = sT[row];
            float v0 = __cosf(t * sW[kk]     + sBt[kk]);
            float v1 = __cosf(t * sW[kk + 1] + sBt[kk + 1]);
            int addr = ((ks * 8 + mt) * 32 + (r & 7) * 4 + (p & 3)) * 4
                     + (r >> 3) + 2 * ((p >> 2) & 1);
            sA[addr] = pack2(v0, v1);
        }
    } else {
        int k0 = sub * 32 - 64;
        int R0 = tid >> 3, c4 = tid & 7;
#pragma unroll
        for (int i = 0; i < 4; i++) {
            int row = R0 + 32 * i;
            float4 v = *(const float4*)&ef[(size_t)(e0 + row) * DEF + k0 + c4 * 4];
            stA_f16(sA, i, v);
        }
    }
}

// ---- warp-tile 32x64 chunk over K=64 (4 fp16 mma k-steps) ----
__device__ __forceinline__ void chunk_mma(const uint32_t* sA, const uint32_t* sB,
                                          int warpM, int warpN, int lane,
                                          float acc[2][8][4]) {
#pragma unroll
    for (int ks = 0; ks < 4; ks++) {
        uint32_t af[2][4];
#pragma unroll
        for (int m = 0; m < 2; m++)
            *(uint4*)af[m] = *(const uint4*)&sA[((ks * 8 + warpM * 2 + m) * 32 + lane) * 4];
        uint32_t bf[8][2];
#pragma unroll
        for (int j = 0; j < 8; j++)
            *(uint2*)bf[j] = *(const uint2*)&sB[((ks * 16 + warpN * 8 + j) * 32 + lane) * 2];
#pragma unroll
        for (int m = 0; m < 2; m++)
#pragma unroll
            for (int j = 0; j < 8; j++) mma_f16(acc[m][j], af[m], bf[j]);
    }
}

// ---------------- node GEMMs: Q,K,V,skip (folds g_acc + g_denom zeroing) -----
__global__ __launch_bounds__(256, 2)
void k_node_mma(const float* __restrict__ X,
                const float* __restrict__ Wq, const float* __restrict__ Wk,
                const float* __restrict__ Wv, const float* __restrict__ Ws,
                const float* __restrict__ bq, const float* __restrict__ bk,
                const float* __restrict__ bv, const float* __restrict__ bs,
                float* __restrict__ out) {
    extern __shared__ char smem[];
    const int tid = threadIdx.x, wid = tid >> 5, lane = tid & 31;
    const int warpM = wid & 3, warpN = wid >> 2;
    const int m0 = blockIdx.y * 128;
    const int bx = blockIdx.x, mat = bx >> 1, n0 = (bx & 1) * 128;
    const float* W; const float* bias; float* dst;
    if      (mat == 0) { W = Wq; bias = bq; dst = g_Q; }
    else if (mat == 1) { W = Wk; bias = bk; dst = g_K; }
    else if (mat == 2) { W = Wv; bias = bv; dst = g_V; }
    else               { W = Ws; bias = bs; dst = out; }

    if (bx == 4) {
        int i4 = m0 * 2 + tid;
        if (i4 < NN * H / 4)
            ((float4*)g_denom)[i4] = make_float4(0.f, 0.f, 0.f, 0.f);
    }

    uint32_t* sA[2] = { (uint32_t*)(smem + SM_A0), (uint32_t*)(smem + SM_A1) };
    uint32_t* sB[2] = { (uint32_t*)(smem + SM_B0), (uint32_t*)(smem + SM_B1) };

    float acc[2][8][4] = {};

    stage_A_node(sA[0],        X, m0, 0);
    stage_A_node(sA[0] + KS32, X, m0, 32);
    stage_B_w(sB[0],        W, n0, 0,  DN);
    stage_B_w(sB[0] + KS32, W, n0, 32, DN);
    __syncthreads();

    for (int c = 0; c < 4; c++) {
        chunk_mma(sA[c & 1], sB[c & 1], warpM, warpN, lane, acc);
        if (c < 3) {
            int k0 = (c + 1) * 64;
            stage_A_node(sA[(c + 1) & 1],        X, m0, k0);
            stage_A_node(sA[(c + 1) & 1] + KS32, X, m0, k0 + 32);
            stage_B_w(sB[(c + 1) & 1],        W, n0, k0,      DN);
            stage_B_w(sB[(c + 1) & 1] + KS32, W, n0, k0 + 32, DN);
        }
        __syncthreads();
    }

    float2 bb[8];
#pragma unroll
    for (int j = 0; j < 8; j++)
        bb[j] = *(const float2*)&bias[n0 + warpN * 64 + j * 8 + (lane & 3) * 2];
#pragma unroll
    for (int m = 0; m < 2; m++)
#pragma unroll
        for (int rv = 0; rv < 2; rv++) {
            int node = m0 + warpM * 32 + m * 16 + rv * 8 + (lane >> 2);
            if (node >= NN) continue;
            size_t off = (size_t)node * DN + n0 + warpN * 64 + (lane & 3) * 2;
            float* dp = dst + off;
#pragma unroll
            for (int j = 0; j < 8; j++) {
                float2 o = make_float2(acc[m][j][rv * 2 + 0] + bb[j].x,
                                       acc[m][j][rv * 2 + 1] + bb[j].y);
                *(float2*)(dp + j * 8) = o;
            }
            if (mat == 2) {
                float* zp = g_acc + off;
#pragma unroll
                for (int j = 0; j < 8; j++)
                    *(float2*)(zp + j * 8) = make_float2(0.f, 0.f);
            }
        }
}

// ------- edge GEMM + fused time-enc + alpha + exp + scatter-aggregate -------
__global__ __launch_bounds__(256, 2)
void k_edge_mma(const float* __restrict__ ef, const int* __restrict__ etup,
                const float* __restrict__ We, const float* __restrict__ times,
                const float* __restrict__ wt, const float* __restrict__ bt) {
    extern __shared__ char smem[];
    const int tid = threadIdx.x, wid = tid >> 5, lane = tid & 31;
    const int warpM = wid & 3, warpN = wid >> 2;
    const int e0 = blockIdx.y * 128;
    const int n0 = blockIdx.x * 128;

    if (tid < 128) ((float*)(smem + SM_T))[tid] = times[e0 + tid];
    if (tid < 64) {
        ((float*)(smem + SM_W))[tid]  = wt[tid];
        ((float*)(smem + SM_BT))[tid] = bt[tid];
    }
    __syncthreads();

    uint32_t* sA[2] = { (uint32_t*)(smem + SM_A0), (uint32_t*)(smem + SM_A1) };
    uint32_t* sB[2] = { (uint32_t*)(smem + SM_B0), (uint32_t*)(smem + SM_B1) };

    float acc[2][8][4] = {};

    stage_A_edge32(sA[0],        smem, ef, e0, 0);
    stage_A_edge32(sA[0] + KS32, smem, ef, e0, 1);
    stage_B_w(sB[0],        We, n0, 0,  DEIN);
    stage_B_w(sB[0] + KS32, We, n0, 32, DEIN);
    __syncthreads();

    for (int c = 0; c < 3; c++) {
        chunk_mma(sA[c & 1], sB[c & 1], warpM, warpN, lane, acc);
        if (c < 2) {
            int k0 = (c + 1) * 64;
            stage_A_edge32(sA[(c + 1) & 1],        smem, ef, e0, 2 * (c + 1));
            stage_A_edge32(sA[(c + 1) & 1] + KS32, smem, ef, e0, 2 * (c + 1) + 1);
            stage_B_w(sB[(c + 1) & 1],        We, n0, k0,      DEIN);
            stage_B_w(sB[(c + 1) & 1] + KS32, We, n0, k0 + 32, DEIN);
        }
        __syncthreads();
    }

    // ---- transpose acc fragments into smem ep tile ----
    float* sEp = (float*)(smem + SM_A0);
#pragma unroll
    for (int m = 0; m < 2; m++)
#pragma unroll
        for (int rv = 0; rv < 2; rv++) {
            int row = warpM * 32 + m * 16 + rv * 8 + (lane >> 2);
            int col = warpN * 64 + (lane & 3) * 2;
#pragma unroll
            for (int j = 0; j < 8; j++)
                *(float2*)&sEp[row * EP_STRIDE + col + j * 8] =
                    make_float2(acc[m][j][rv * 2 + 0], acc[m][j][rv * 2 + 1]);
        }
    __syncthreads();

    // ---- warp-per-edge epilogue, unroll 4 for deep gather MLP ----
    const float scale = 0.17677669529663687f;
    const int hb = (n0 >> 5) + (lane >> 3);
    const int colg = n0 + lane * 4;

    int my_sd = etup[(lane >> 4) * EE + e0 + wid * 16 + (lane & 15)];

#pragma unroll
    for (int t = 0; t < 16; t += 4) {
        int s[4], d[4];
#pragma unroll
        for (int u = 0; u < 4; u++) {
            s[u] = __shfl_sync(0xffffffffu, my_sd, t + u);
            d[u] = __shfl_sync(0xffffffffu, my_sd, 16 + t + u);
        }
        float4 ep[4], qv[4], kv[4], vv[4];
#pragma unroll
        for (int u = 0; u < 4; u++) {
            int eloc = wid * 16 + t + u;
            ep[u] = *(const float4*)&sEp[eloc * EP_STRIDE + lane * 4];
            qv[u] = *(const float4*)&g_Q[(size_t)d[u] * DN + colg];
            kv[u] = *(const float4*)&g_K[(size_t)s[u] * DN + colg];
            vv[u] = *(const float4*)&g_V[(size_t)s[u] * DN + colg];
        }
        float p[4];
#pragma unroll
        for (int u = 0; u < 4; u++)
            p[u] = qv[u].x * (kv[u].x + ep[u].x) + qv[u].y * (kv[u].y + ep[u].y)
                 + qv[u].z * (kv[u].z + ep[u].z) + qv[u].w * (kv[u].w + ep[u].w);
#pragma unroll
        for (int m = 1; m <= 4; m <<= 1)
#pragma unroll
            for (int u = 0; u < 4; u++)
                p[u] += __shfl_xor_sync(0xffffffffu, p[u], m);
#pragma unroll
        for (int u = 0; u < 4; u++) {
            float wgt = __expf(p[u] * scale);
            float4 r = make_float4(wgt * (vv[u].x + ep[u].x),
                                   wgt * (vv[u].y + ep[u].y),
                                   wgt * (vv[u].z + ep[u].z),
                                   wgt * (vv[u].w + ep[u].w));
            red_add_v4(&g_acc[(size_t)d[u] * DN + colg], r);
            if ((lane & 7) == 0) red_add_f(&g_denom[d[u] * H + hb], wgt);
        }
    }
}

// ---------------- finalize: out = skip + acc/denom ---------------------------
__global__ __launch_bounds__(256)
void k_finalize(float* __restrict__ out) {
    int idx = blockIdx.x * blockDim.x + threadIdx.x;
    if (idx >= NN * DN / 4) return;
    int node = idx >> 6;
    int col4 = idx & 63;
    int head = col4 >> 3;
    float den = g_denom[node * H + head] + 1e-16f;
    float inv = 1.0f / den;
    float4 a = ((const float4*)g_acc)[idx];
    float4 o = ((float4*)out)[idx];
    o.x += a.x * inv; o.y += a.y * inv; o.z += a.z * inv; o.w += a.w * inv;
    ((float4*)out)[idx] = o;
}

// ---------------- launch ----------------------------------------------------
extern "C" void kernel_launch(void* const* d_in, const int* in_sizes, int n_in,
                              void* d_out, int out_size) {
    const int*   etup       = (const int*)  d_in[0];
    const float* edge_feats = (const float*)d_in[1];
    const float* times      = (const float*)d_in[2];
    const float* X          = (const float*)d_in[3];
    const float* w_time     = (const float*)d_in[4];
    const float* b_time     = (const float*)d_in[5];
    const float* Wq         = (const float*)d_in[6];
    const float* bq         = (const float*)d_in[7];
    const float* Wk         = (const float*)d_in[8];
    const float* bk         = (const float*)d_in[9];
    const float* Wv         = (const float*)d_in[10];
    const float* bv         = (const float*)d_in[11];
    const float* We         = (const float*)d_in[12];
    const float* Ws         = (const float*)d_in[13];
    const float* bs         = (const float*)d_in[14];
    float* out = (float*)d_out;

    cudaFuncSetAttribute(k_node_mma, cudaFuncAttributeMaxDynamicSharedMemorySize, SMEM_NODE);
    cudaFuncSetAttribute(k_edge_mma, cudaFuncAttributeMaxDynamicSharedMemorySize, SMEM_EDGE);

    k_node_mma<<<dim3(8, (NN + 127) / 128), 256, SMEM_NODE>>>(
        X, Wq, Wk, Wv, Ws, bq, bk, bv, bs, out);
    k_edge_mma<<<dim3(2, EE / 128), 256, SMEM_EDGE>>>(
        edge_feats, etup, We, times, w_time, b_time);
    k_finalize<<<(NN * DN / 4 + 255) / 256, 256>>>(out);
}